// round 13
// baseline (speedup 1.0000x reference)
#include <cuda_runtime.h>
#include <math.h>

#define NX 400
#define NY 400
#define NC (NX*NY)
#define STEPS 300
#define NSTRIP 134
#define NBLK (2*NSTRIP)
#define TPB 320
#define MAXH 3
#define SRC_I 30
#define DET_I 370
#define PI_F 3.14159265358979323846f
#define NSLOT 200                  // 2 columns per 16B slot

typedef unsigned long long u64;

// Persistent device state (no allocations allowed)
__device__ float d_ie[NC];                 // COURANT / eps
__device__ float d_damp1[NX];              // 1-D damp profile (x == y)
__device__ float4 d_slT[2*NBLK*NSLOT];     // [parity][blk][slot]: top-row Ez, tag-fused
__device__ float4 d_slB[2*NBLK*NSLOT];     // bottom-row Ez, tag-fused

// GPU-scope relaxed 16B exchange ops (stay in L2)
__device__ __forceinline__ float4 ld_gpu_v4(const float4* p) {
    float4 v;
    asm volatile("ld.relaxed.gpu.global.v4.f32 {%0,%1,%2,%3}, [%4];"
                 : "=f"(v.x), "=f"(v.y), "=f"(v.z), "=f"(v.w) : "l"(p) : "memory");
    return v;
}
__device__ __forceinline__ void st_gpu_v4(float4* p, float4 v) {
    asm volatile("st.relaxed.gpu.global.v4.f32 [%0], {%1,%2,%3,%4};"
                 :: "l"(p), "f"(v.x), "f"(v.y), "f"(v.z), "f"(v.w) : "memory");
}

// ---- packed f32x2 helpers ----
__device__ __forceinline__ u64 pk(float a, float b) {
    u64 r; asm("mov.b64 %0, {%1, %2};" : "=l"(r) : "f"(a), "f"(b)); return r;
}
__device__ __forceinline__ void upk(u64 v, float& a, float& b) {
    asm("mov.b64 {%0, %1}, %2;" : "=f"(a), "=f"(b) : "l"(v));
}
__device__ __forceinline__ u64 f2sub(u64 a, u64 b) {
    u64 d; asm("sub.rn.f32x2 %0, %1, %2;" : "=l"(d) : "l"(a), "l"(b)); return d;
}
__device__ __forceinline__ u64 f2mul(u64 a, u64 b) {
    u64 d; asm("mul.rn.f32x2 %0, %1, %2;" : "=l"(d) : "l"(a), "l"(b)); return d;
}
__device__ __forceinline__ u64 f2fma(u64 a, u64 b, u64 c) {
    u64 d; asm("fma.rn.f32x2 %0, %1, %2, %3;" : "=l"(d) : "l"(a), "l"(b), "l"(c)); return d;
}

// ---------------- setup: eps, damp, zero slot buffers ----------------
__global__ void setup_kernel(const float* __restrict__ radius) {
    int idx = blockIdx.x * blockDim.x + threadIdx.x;
    if (idx < 2*NBLK*NSLOT) {
        d_slT[idx] = make_float4(0.f, 0.f, 0.f, 0.f);   // tag 0 == "step 0 published", Ez=0
        d_slB[idx] = make_float4(0.f, 0.f, 0.f, 0.f);
    }
    if (idx < NX) {
        float v = 1.0f;
        if (idx < 10) {
            float rr = (10 - idx - 0.5f) * 0.1f;
            v = expf(-0.5f * rr * rr * rr);
        } else if (idx >= NX - 10) {
            float rr = (10 - (NX - 1 - idx) - 0.5f) * 0.1f;
            v = expf(-0.5f * rr * rr * rr);
        }
        d_damp1[idx] = v;
    }
    if (idx >= NC) return;
    int i = idx / NY;
    int j = idx - i * NY;
    int p   = (j + 10) / 80 - 1;
    int off = (j + 10) - 80 * (p + 1);
    bool inport = (p >= 0 && p < 4 && off < 20);
    float eps = 1.0f;
    if ((i < SRC_I || i >= DET_I) && inport) eps = 2.8f;
    if (i >= 80 && i < 320 && j >= 80 && j < 320) {
        int X = i - 80, Y = j - 80;
        int a = X / 30, b = Y / 30;
        float r = radius[a * 8 + b];
        if (r < 0.3f) r = 0.0f;
        float dx = (float)(X - (15 + 30 * a));
        float dy = (float)(Y - (15 + 30 * b));
        eps = (dx * dx + dy * dy <= r * r) ? 1.0f : 2.8f;
    }
    d_ie[idx] = 0.5f / eps;
}

// ---------- persistent strip kernel: 2 blocks/SM, f32x2 quads, prefetched exchange ----------
__global__ void __launch_bounds__(TPB, 2)
fdtd_kernel(const float* __restrict__ phases, float* __restrict__ out)
{
    __shared__ __align__(16) float sEz[2*MAXH*NY];   // parity double-buffered Ez

    const int bk    = blockIdx.x;
    const int batch = bk / NSTRIP;
    const int s     = bk - batch * NSTRIP;
    const int r0    = (s * NX) / NSTRIP;
    const int r1    = ((s + 1) * NX) / NSTRIP;
    const int h     = r1 - r0;
    const bool hasA = (s > 0);
    const bool hasB = (s < NSTRIP - 1);
    const int tid   = threadIdx.x;
    const int bkA   = hasA ? bk - 1 : bk;
    const int bkB   = hasB ? bk + 1 : bk;

    // warp-priority permutation: boundary rows to highest active warps (hi-wid-first arbiter)
    const int  li   = tid / 100;
    const int  jq   = tid - li * 100;
    const bool act  = (li < h);
    int l;
    if (li == h - 2)      l = 0;       // top row -> higher warps
    else if (li == h - 1) l = h - 1;   // bottom row -> highest warps
    else                  l = li + 1;  // interior
    if (!act) l = 0;

    const int  i    = r0 + l;
    const int  j0   = jq * 4;
    const int  o    = l * NY + j0;
    const bool topT = act && (l == 0);
    const bool botT = act && (l == h - 1);
    const bool spinA = topT && hasA;
    const bool spinB = botT && hasB;
    const bool upReg  = act && (l > 0);
    const bool dnReg  = act && (l < h - 1);
    const bool edgeTop = topT && !hasA;
    const bool edgeL   = (jq == 0);

    for (int x = tid; x < 2*MAXH*NY; x += TPB) sEz[x] = 0.f;

    // tag-fused slot pointers (parity offset added per step)
    const float4* plA = d_slB + bkA*NSLOT + 2*jq;   // above's bottom Ez slots
    const float4* plB = d_slT + bkB*NSLOT + 2*jq;   // below's top Ez slots
    float4*       psT = d_slT + bk*NSLOT + 2*jq;    // own top publish
    float4*       psB = d_slB + bk*NSLOT + 2*jq;    // own bottom publish

    // packed state
    u64 ez01 = 0, ez23 = 0, hx01 = 0, hx23 = 0, hy01 = 0, hy23 = 0, hyU01 = 0, hyU23 = 0;
    float hxW = 0.f;
    // packed constants
    u64 c_dmp01 = 0, c_dmp23 = 0, c_iek01 = 0, c_iek23 = 0, c_rU2 = 0;
    const u64 c_half  = pk(0.5f, 0.5f);
    const u64 c_nhalf = pk(-0.5f, -0.5f);
    float rLdmp = 0.f;
    float4 Ssin = {0,0,0,0}, Scos = {0,0,0,0};
    bool hasSrc = false, hasDet = false;

    if (act) {
        float di = d_damp1[i];
        float dmp0 = di * d_damp1[j0],   dmp1 = di * d_damp1[j0+1];
        float dmp2 = di * d_damp1[j0+2], dmp3 = di * d_damp1[j0+3];
        c_dmp01 = pk(dmp0, dmp1); c_dmp23 = pk(dmp2, dmp3);
        float4 iek = *(const float4*)&d_ie[i * NY + j0];
        c_iek01 = pk(iek.x, iek.y); c_iek23 = pk(iek.z, iek.w);
        float rU = (i > 0) ? d_damp1[i - 1] / di : 1.f;
        c_rU2 = pk(rU, rU);
        float rL = (j0 > 0) ? d_damp1[j0 - 1] / d_damp1[j0] : 1.f;
        rLdmp = rL * dmp0;
        if (i == SRC_I || i == DET_I) {
            float* ss = &Ssin.x; float* sc = &Scos.x;
            #pragma unroll
            for (int c = 0; c < 4; ++c) {
                int j = j0 + c;
                int p = (j + 10) / 80 - 1;
                int o2 = (j + 10) - 80 * (p + 1);
                bool inport = (p >= 0 && p < 4 && o2 < 20);
                if (inport && i == SRC_I) {
                    float ps = PI_F * phases[batch * 4 + p];
                    ss[c] = sinf(ps);     // angle at t=1 (tf=0)
                    sc[c] = cosf(ps);
                    hasSrc = true;
                }
                if (inport && i == DET_I) hasDet = true;
            }
        }
    }
    const float W  = (float)(2.0 * 3.14159265358979323846 * (12.5 / 1550.0));
    const float cW = cosf(W), sW = sinf(W);
    __syncthreads();

    // prime the prefetch pipeline: loads for parity 0 (step 1 reads qo=0; init tags==0 are valid)
    float4 a0 = {0,0,0,0}, a1 = {0,0,0,0}, b0 = {0,0,0,0}, b1 = {0,0,0,0};
    if (spinA) { a0 = ld_gpu_v4(plA); a1 = ld_gpu_v4(plA + 1); }
    if (spinB) { b0 = ld_gpu_v4(plB); b1 = ld_gpu_v4(plB + 1); }

    for (unsigned t = 1; t <= STEPS; ++t) {
        const int qo = (int)((t - 1) & 1u) * (NBLK*NSLOT);
        const int po = (int)(t & 1u) * (NBLK*NSLOT);
        const float tf1  = (float)(t - 1);    // tag we need from neighbors
        const float tagf = (float)t;          // tag we publish
        const float* bufQ = sEz + (int)((t - 1) & 1u) * (MAXH*NY);
        float*       bufP = sEz + (int)(t & 1u) * (MAXH*NY);

        // ---- unpack own Ez(t-1); gather neighbors from smem ----
        float e0, e1, e2, e3;
        upk(ez01, e0, e1); upk(ez23, e2, e3);
        float ezL = e0, ezE = e3;
        u64 ezU01 = ez01, ezU23 = ez23, ezD01 = ez01, ezD23 = ez23;
        if (act) {
            if (!edgeL)  ezL = bufQ[o - 1];
            if (jq < 99) ezE = bufQ[o + 4];
            if (upReg) { ulonglong2 u = *(const ulonglong2*)&bufQ[o - NY]; ezU01 = u.x; ezU23 = u.y; }
            if (dnReg) { ulonglong2 u = *(const ulonglong2*)&bufQ[o + NY]; ezD01 = u.x; ezD23 = u.y; }
        }
        // ---- consume prefetched slots; on stale tag fall back to poll loop ----
        if (spinA) {
            while (a0.x < tf1 || a0.w < tf1 || a1.x < tf1 || a1.w < tf1) {
                a0 = ld_gpu_v4(plA + qo); a1 = ld_gpu_v4(plA + qo + 1);
            }
            ezU01 = pk(a0.y, a0.z); ezU23 = pk(a1.y, a1.z);
        }
        if (spinB) {
            while (b0.x < tf1 || b0.w < tf1 || b1.x < tf1 || b1.w < tf1) {
                b0 = ld_gpu_v4(plB + qo); b1 = ld_gpu_v4(plB + qo + 1);
            }
            ezD01 = pk(b0.y, b0.z); ezD23 = pk(b1.y, b1.z);
        }

        if (act) {
            const u64 ezR01 = pk(e1, e2);
            const u64 ezR23 = pk(e3, ezE);

            // ---- H phase (identical rounding to scalar version) ----
            hx01 = f2mul(c_dmp01, f2fma(c_nhalf, f2sub(ezR01, ez01), hx01));
            hx23 = f2mul(c_dmp23, f2fma(c_nhalf, f2sub(ezR23, ez23), hx23));
            hy01 = f2mul(c_dmp01, f2fma(c_half, f2sub(ezD01, ez01), hy01));
            hy23 = f2mul(c_dmp23, f2fma(c_half, f2sub(ezD23, ez23), hy23));
            hyU01 = f2mul(c_rU2, f2mul(c_dmp01, f2fma(c_half, f2sub(ez01, ezU01), hyU01)));
            hyU23 = f2mul(c_rU2, f2mul(c_dmp23, f2fma(c_half, f2sub(ez23, ezU23), hyU23)));
            hxW = rLdmp * __fmaf_rn(-0.5f, e0 - ezL, hxW);

            // ---- E phase: all registers ----
            float h0, h1, h2, h3;
            upk(hx01, h0, h1); upk(hx23, h2, h3);
            const u64 hxL01 = pk(edgeL ? h0 : hxW, h0);
            const u64 hxL23 = pk(h1, h2);
            const u64 hyUe01 = edgeTop ? hy01 : hyU01;
            const u64 hyUe23 = edgeTop ? hy23 : hyU23;
            u64 d01 = f2sub(f2sub(hy01, hyUe01), f2sub(hx01, hxL01));
            u64 d23 = f2sub(f2sub(hy23, hyUe23), f2sub(hx23, hxL23));
            ez01 = f2mul(c_dmp01, f2fma(c_iek01, d01, ez01));
            ez23 = f2mul(c_dmp23, f2fma(c_iek23, d23, ez23));

            if (hasSrc) {
                float g0, g1, g2, g3;
                upk(ez01, g0, g1); upk(ez23, g2, g3);
                g0 += Ssin.x; g1 += Ssin.y; g2 += Ssin.z; g3 += Ssin.w;
                ez01 = pk(g0, g1); ez23 = pk(g2, g3);
                float ns, nc;
                ns = Ssin.x * cW + Scos.x * sW; nc = Scos.x * cW - Ssin.x * sW; Ssin.x = ns; Scos.x = nc;
                ns = Ssin.y * cW + Scos.y * sW; nc = Scos.y * cW - Ssin.y * sW; Ssin.y = ns; Scos.y = nc;
                ns = Ssin.z * cW + Scos.z * sW; nc = Scos.z * cW - Ssin.z * sW; Ssin.z = ns; Scos.z = nc;
                ns = Ssin.w * cW + Scos.w * sW; nc = Scos.w * cW - Ssin.w * sW; Ssin.w = ns; Scos.w = nc;
            }

            // ---- publish boundary quads ASAP (protocol covers WAR on parity slots) ----
            if (topT | botT) {
                float p0, p1, p2, p3;
                upk(ez01, p0, p1); upk(ez23, p2, p3);
                if (topT) {
                    st_gpu_v4(psT + po,     make_float4(tagf, p0, p1, tagf));
                    st_gpu_v4(psT + po + 1, make_float4(tagf, p2, p3, tagf));
                }
                if (botT) {
                    st_gpu_v4(psB + po,     make_float4(tagf, p0, p1, tagf));
                    st_gpu_v4(psB + po + 1, make_float4(tagf, p2, p3, tagf));
                }
            }
            ulonglong2 st2; st2.x = ez01; st2.y = ez23;
            *(ulonglong2*)&bufP[o] = st2;
        }

        // ---- prefetch next step's halo slots (parity po); latency hidden by the bar ----
        if (spinA) { a0 = ld_gpu_v4(plA + po); a1 = ld_gpu_v4(plA + po + 1); }
        if (spinB) { b0 = ld_gpu_v4(plB + po); b1 = ld_gpu_v4(plB + po + 1); }

        __syncthreads();
    }

    // ---- detector: final Ez at row 370 lives in registers ----
    if (hasDet) {
        float e0, e1, e2, e3;
        upk(ez01, e0, e1); upk(ez23, e2, e3);
        float ec[4] = {e0, e1, e2, e3};
        #pragma unroll
        for (int c = 0; c < 4; ++c) {
            int j = j0 + c;
            int p = (j + 10) / 80 - 1;
            int o2 = (j + 10) - 80 * (p + 1);
            if (p >= 0 && p < 4 && o2 < 20)
                out[batch * 80 + p * 20 + o2] = ec[c];
        }
    }
}

extern "C" void kernel_launch(void* const* d_in, const int* in_sizes, int n_in,
                              void* d_out, int out_size) {
    const float* phases = (const float*)d_in[0];   // (2,4)
    const float* radius = (const float*)d_in[1];   // (8,8)
    float* out = (float*)d_out;                    // (2,4,20)
    setup_kernel<<<(NC + 255) / 256, 256>>>(radius);
    fdtd_kernel<<<NBLK, TPB>>>(phases, out);
}